// round 1
// baseline (speedup 1.0000x reference)
#include <cuda_runtime.h>
#include <math.h>

#define BB 4
#define SS 4096
#define EE 512
#define DD 64

// Scratch for projected Q, K, V (allocation-free: device globals)
__device__ float g_Q[BB * SS * DD];
__device__ float g_K[BB * SS * DD];
__device__ float g_V[BB * SS * DD];

// ---------------------------------------------------------------------------
// QKV projection: C[16384,192] = X[16384,512] @ [Wq|Wk|Wv] + bias
// Block: 64 rows x 192 cols, 256 threads, e-chunks of 32 staged in SMEM.
// ---------------------------------------------------------------------------
__global__ __launch_bounds__(256) void qkv_kernel(
    const float* __restrict__ X,
    const float* __restrict__ Wq, const float* __restrict__ bq,
    const float* __restrict__ Wk, const float* __restrict__ bk,
    const float* __restrict__ Wv, const float* __restrict__ bv)
{
    __shared__ float xs[32][65];    // transposed X chunk: xs[e][row]
    __shared__ float ws[32][192];   // weight chunk: ws[e][col]

    const int t   = threadIdx.x;
    const int tr  = t >> 5;         // 0..7  (row group)
    const int tc  = t & 31;         // 0..31 (col base)
    const int row0 = blockIdx.x * 64;

    float acc[8][6];
#pragma unroll
    for (int i = 0; i < 8; i++)
#pragma unroll
        for (int m = 0; m < 6; m++) acc[i][m] = 0.f;

    for (int e0 = 0; e0 < EE; e0 += 32) {
        __syncthreads();
        // Load X chunk (64 rows x 32 e), transposed into xs[e][r]
#pragma unroll
        for (int k = 0; k < 2; k++) {
            int idx = t + k * 256;          // 0..511 (float4 index)
            int r   = idx >> 3;             // 0..63
            int e4  = idx & 7;              // 0..7
            float4 v = *(const float4*)&X[(row0 + r) * EE + e0 + e4 * 4];
            xs[e4 * 4 + 0][r] = v.x;
            xs[e4 * 4 + 1][r] = v.y;
            xs[e4 * 4 + 2][r] = v.z;
            xs[e4 * 4 + 3][r] = v.w;
        }
        // Load W chunk (32 e x 192 cols)
        for (int idx = t; idx < 32 * 192; idx += 256) {
            int e = idx / 192;
            int j = idx - e * 192;
            float w;
            if (j < 64)       w = Wq[(e0 + e) * 64 + j];
            else if (j < 128) w = Wk[(e0 + e) * 64 + (j - 64)];
            else              w = Wv[(e0 + e) * 64 + (j - 128)];
            ws[e][j] = w;
        }
        __syncthreads();

#pragma unroll 8
        for (int e = 0; e < 32; e++) {
            float xv[8];
#pragma unroll
            for (int i = 0; i < 8; i++) xv[i] = xs[e][tr * 8 + i];
            float wv[6];
#pragma unroll
            for (int m = 0; m < 6; m++) wv[m] = ws[e][tc + 32 * m];
#pragma unroll
            for (int i = 0; i < 8; i++)
#pragma unroll
                for (int m = 0; m < 6; m++)
                    acc[i][m] = fmaf(xv[i], wv[m], acc[i][m]);
        }
    }

    // Bias + writeback
    float bias[6];
    bias[0] = bq[tc];      bias[1] = bq[tc + 32];
    bias[2] = bk[tc];      bias[3] = bk[tc + 32];
    bias[4] = bv[tc];      bias[5] = bv[tc + 32];

#pragma unroll
    for (int i = 0; i < 8; i++) {
        int row = row0 + tr * 8 + i;
        g_Q[row * 64 + tc]      = acc[i][0] + bias[0];
        g_Q[row * 64 + tc + 32] = acc[i][1] + bias[1];
        g_K[row * 64 + tc]      = acc[i][2] + bias[2];
        g_K[row * 64 + tc + 32] = acc[i][3] + bias[3];
        g_V[row * 64 + tc]      = acc[i][4] + bias[4];
        g_V[row * 64 + tc + 32] = acc[i][5] + bias[5];
    }
}

// ---------------------------------------------------------------------------
// Flash attention (causal), fp32. TQ=32 queries per 256-thread block, TK=64.
// Thread (ty=t/16, tx=t%16): rows q = ty*2+{0,1}; score cols k = tx+16j;
// output cols d = tx*4+{0..3}.
// ---------------------------------------------------------------------------
#define TQ 32
#define TK 64
#define PAD 68
#define ATTN_SMEM ((TQ * PAD + TK * PAD + TK * PAD + TQ * PAD) * 4)

__global__ __launch_bounds__(256) void attn_kernel(float* __restrict__ out)
{
    extern __shared__ float sm[];
    float* Qs = sm;                        // [32][68]
    float* Ks = Qs + TQ * PAD;             // [64][68]
    float* Vs = Ks + TK * PAD;             // [64][68]
    float* Ps = Vs + TK * PAD;             // [32][68]

    const int t  = threadIdx.x;
    const int ty = t >> 4;                 // 0..15
    const int tx = t & 15;                 // 0..15

    const int bx = blockIdx.x;
    const int b  = bx & 3;
    const int qt = (SS / TQ - 1) - (bx >> 2);   // longest-work blocks first
    const int qbase = qt * TQ;

    // Load Q tile, pre-scaled by 1/sqrt(64)
    {
        const float* Qg = g_Q + (b * SS + qbase) * 64;
#pragma unroll
        for (int k = 0; k < 2; k++) {
            int idx = t + k * 256;          // float4 index, 0..511
            int r = idx >> 4, c4 = idx & 15;
            float4 v = *(const float4*)&Qg[r * 64 + c4 * 4];
            v.x *= 0.125f; v.y *= 0.125f; v.z *= 0.125f; v.w *= 0.125f;
            *(float4*)&Qs[r * PAD + c4 * 4] = v;
        }
    }

    float mrow[2] = {-1e30f, -1e30f};
    float lrow[2] = {0.f, 0.f};
    float o[2][4];
#pragma unroll
    for (int i = 0; i < 2; i++)
#pragma unroll
        for (int j = 0; j < 4; j++) o[i][j] = 0.f;

    const int ntiles = qbase / TK + 1;
    for (int kt = 0; kt < ntiles; kt++) {
        const int kbase = kt * TK;
        __syncthreads();   // protect Ks/Vs (prev AV) before overwrite
        {
            const float* Kg = g_K + (b * SS + kbase) * 64;
            const float* Vg = g_V + (b * SS + kbase) * 64;
#pragma unroll
            for (int k = 0; k < 4; k++) {
                int idx = t + k * 256;          // 0..1023 float4s
                int r = idx >> 4, c4 = idx & 15;
                *(float4*)&Ks[r * PAD + c4 * 4] = *(const float4*)&Kg[r * 64 + c4 * 4];
                *(float4*)&Vs[r * PAD + c4 * 4] = *(const float4*)&Vg[r * 64 + c4 * 4];
            }
        }
        __syncthreads();

        // ---- scores: s[i][j] = (Q/8) . K ----
        float s[2][4];
#pragma unroll
        for (int i = 0; i < 2; i++)
#pragma unroll
            for (int j = 0; j < 4; j++) s[i][j] = 0.f;

#pragma unroll
        for (int d4 = 0; d4 < 16; d4++) {
            float4 q0 = *(const float4*)&Qs[(ty * 2 + 0) * PAD + d4 * 4];
            float4 q1 = *(const float4*)&Qs[(ty * 2 + 1) * PAD + d4 * 4];
#pragma unroll
            for (int j = 0; j < 4; j++) {
                float4 kv = *(const float4*)&Ks[(tx + 16 * j) * PAD + d4 * 4];
                s[0][j] = fmaf(q0.x, kv.x, s[0][j]);
                s[0][j] = fmaf(q0.y, kv.y, s[0][j]);
                s[0][j] = fmaf(q0.z, kv.z, s[0][j]);
                s[0][j] = fmaf(q0.w, kv.w, s[0][j]);
                s[1][j] = fmaf(q1.x, kv.x, s[1][j]);
                s[1][j] = fmaf(q1.y, kv.y, s[1][j]);
                s[1][j] = fmaf(q1.z, kv.z, s[1][j]);
                s[1][j] = fmaf(q1.w, kv.w, s[1][j]);
            }
        }

        // ---- causal mask ----
#pragma unroll
        for (int i = 0; i < 2; i++) {
            int q = qbase + ty * 2 + i;
#pragma unroll
            for (int j = 0; j < 4; j++) {
                int kk = kbase + tx + 16 * j;
                if (kk > q) s[i][j] = -1e30f;
            }
        }

        // ---- row max (reduce over tx group of 16 lanes) ----
        float mt[2];
#pragma unroll
        for (int i = 0; i < 2; i++) {
            mt[i] = fmaxf(fmaxf(s[i][0], s[i][1]), fmaxf(s[i][2], s[i][3]));
        }
#pragma unroll
        for (int off = 1; off < 16; off <<= 1) {
            mt[0] = fmaxf(mt[0], __shfl_xor_sync(0xffffffffu, mt[0], off));
            mt[1] = fmaxf(mt[1], __shfl_xor_sync(0xffffffffu, mt[1], off));
        }

        float alpha[2];
#pragma unroll
        for (int i = 0; i < 2; i++) {
            float mn = fmaxf(mrow[i], mt[i]);
            alpha[i] = __expf(mrow[i] - mn);
            mrow[i] = mn;
        }

        // ---- exponentiate + row sum ----
        float rs[2] = {0.f, 0.f};
#pragma unroll
        for (int i = 0; i < 2; i++)
#pragma unroll
            for (int j = 0; j < 4; j++) {
                s[i][j] = __expf(s[i][j] - mrow[i]);
                rs[i] += s[i][j];
            }
#pragma unroll
        for (int off = 1; off < 16; off <<= 1) {
            rs[0] += __shfl_xor_sync(0xffffffffu, rs[0], off);
            rs[1] += __shfl_xor_sync(0xffffffffu, rs[1], off);
        }
#pragma unroll
        for (int i = 0; i < 2; i++) {
            lrow[i] = lrow[i] * alpha[i] + rs[i];
#pragma unroll
            for (int j = 0; j < 4; j++) o[i][j] *= alpha[i];
        }

        // ---- stage P to smem ----
#pragma unroll
        for (int i = 0; i < 2; i++)
#pragma unroll
            for (int j = 0; j < 4; j++)
                Ps[(ty * 2 + i) * PAD + tx + 16 * j] = s[i][j];
        __syncthreads();

        // ---- O += P @ V ----
#pragma unroll
        for (int k4 = 0; k4 < 16; k4++) {
            float4 p0 = *(const float4*)&Ps[(ty * 2 + 0) * PAD + k4 * 4];
            float4 p1 = *(const float4*)&Ps[(ty * 2 + 1) * PAD + k4 * 4];
            float pa[4] = {p0.x, p0.y, p0.z, p0.w};
            float pb[4] = {p1.x, p1.y, p1.z, p1.w};
#pragma unroll
            for (int kk = 0; kk < 4; kk++) {
                float4 vv = *(const float4*)&Vs[(k4 * 4 + kk) * PAD + tx * 4];
                o[0][0] = fmaf(pa[kk], vv.x, o[0][0]);
                o[0][1] = fmaf(pa[kk], vv.y, o[0][1]);
                o[0][2] = fmaf(pa[kk], vv.z, o[0][2]);
                o[0][3] = fmaf(pa[kk], vv.w, o[0][3]);
                o[1][0] = fmaf(pb[kk], vv.x, o[1][0]);
                o[1][1] = fmaf(pb[kk], vv.y, o[1][1]);
                o[1][2] = fmaf(pb[kk], vv.z, o[1][2]);
                o[1][3] = fmaf(pb[kk], vv.w, o[1][3]);
            }
        }
    }

    // ---- epilogue: normalize + store ----
#pragma unroll
    for (int i = 0; i < 2; i++) {
        float inv = 1.f / lrow[i];
        float4 r;
        r.x = o[i][0] * inv;
        r.y = o[i][1] * inv;
        r.z = o[i][2] * inv;
        r.w = o[i][3] * inv;
        *(float4*)&out[(b * SS + qbase + ty * 2 + i) * 64 + tx * 4] = r;
    }
}

// ---------------------------------------------------------------------------
extern "C" void kernel_launch(void* const* d_in, const int* in_sizes, int n_in,
                              void* d_out, int out_size)
{
    const float* X  = (const float*)d_in[0];
    const float* Wq = (const float*)d_in[1];
    const float* bq = (const float*)d_in[2];
    const float* Wk = (const float*)d_in[3];
    const float* bk = (const float*)d_in[4];
    const float* Wv = (const float*)d_in[5];
    const float* bv = (const float*)d_in[6];
    float* out = (float*)d_out;

    cudaFuncSetAttribute(attn_kernel,
                         cudaFuncAttributeMaxDynamicSharedMemorySize, ATTN_SMEM);

    qkv_kernel<<<(BB * SS) / 64, 256>>>(X, Wq, bq, Wk, bk, Wv, bv);
    attn_kernel<<<BB * (SS / TQ), 256, ATTN_SMEM>>>(out);
}